// round 4
// baseline (speedup 1.0000x reference)
#include <cuda_runtime.h>
#include <math.h>

#define BQ   16
#define TT   1000
#define MEL  80
#define HID  512
#define NCLS 64
#define NROW (BQ*TT)

#define SER_NCTA    128
#define SER_NC      4          // HID / SER_NCTA
#define SER_THREADS 256

// ---------------- scratch (static device globals; no allocations) ----------------
__device__ float g_be0[NROW*HID];     // base_eff of layer0 == input to layer1
__device__ float g_be1[NROW*HID];     // base_eff of layer1 (second half of ys)
__device__ float g_h1 [NROW*HID];     // h1 trace (first half of ys)
__device__ float g_xs1[NROW];         // per-(b,t) x_scale for layer1
__device__ float g_h  [BQ*HID];       // current h1
__device__ float g_err[BQ*HID];       // current error vector
__device__ float g_norm2[2][BQ];      // rotating squared-norm accumulators
__device__ unsigned g_bcount;         // grid barrier counter (monotonic per launch)

__device__ __forceinline__ float sigm(float x){ return 1.0f/(1.0f+expf(-x)); }

// ---------------- init: reset cross-launch state ----------------
__global__ void k_init(){
  int i = threadIdx.x;
  if (i==0) g_bcount = 0u;
  if (i<2*BQ) (&g_norm2[0][0])[i] = 0.f;
  for (int j=i; j<BQ*HID; j+=blockDim.x) g_h[j]=0.f;
}

// ---------------- be0 = clip(feats/||feats||) @ B0^T ; xs1 = ||be0|| ----------------
__global__ __launch_bounds__(256) void k_be0(const float* __restrict__ feats,
                                             const float* __restrict__ B0){
  __shared__ float xn[16][MEL];
  __shared__ float snorm[16];
  __shared__ float sxs[16];
  int tid = threadIdx.x;
  int row0 = blockIdx.x*16;
  for (int i=tid;i<16*MEL;i+=256)
    xn[i/MEL][i%MEL] = feats[row0*MEL + i];
  __syncthreads();
  if (tid<16){
    float s=0.f;
    #pragma unroll
    for (int k=0;k<MEL;k++){ float v=xn[tid][k]; s+=v*v; }
    sxs[tid]=fmaxf(sqrtf(s),1e-6f);
    snorm[tid]=0.f;
  }
  __syncthreads();
  for (int i=tid;i<16*MEL;i+=256){
    int r=i/MEL;
    float v = xn[r][i%MEL]/sxs[r];
    xn[r][i%MEL] = fminf(fmaxf(v,-1.f),1.f);
  }
  __syncthreads();
  int n0=tid, n1=tid+256;
  float a0[16], a1_[16];
  #pragma unroll
  for (int r=0;r<16;r++){ a0[r]=0.f; a1_[r]=0.f; }
  for (int k=0;k<MEL;k+=4){
    float4 w0 = *(const float4*)&B0[n0*MEL+k];
    float4 w1 = *(const float4*)&B0[n1*MEL+k];
    #pragma unroll
    for (int r=0;r<16;r++){
      float4 x = *(const float4*)&xn[r][k];
      a0 [r] += w0.x*x.x + w0.y*x.y + w0.z*x.z + w0.w*x.w;
      a1_[r] += w1.x*x.x + w1.y*x.y + w1.z*x.z + w1.w*x.w;
    }
  }
  #pragma unroll
  for (int r=0;r<16;r++){
    g_be0[(row0+r)*HID+n0]=a0[r];
    g_be0[(row0+r)*HID+n1]=a1_[r];
    atomicAdd(&snorm[r], a0[r]*a0[r] + a1_[r]*a1_[r]);
  }
  __syncthreads();
  if (tid<16) g_xs1[row0+tid] = fmaxf(sqrtf(snorm[tid]),1e-6f);
}

// ---------------- be1 = clip(be0/xs1) @ B1^T ----------------
__global__ __launch_bounds__(256) void k_be1(const float* __restrict__ B1){
  __shared__ float xn[16][HID];
  __shared__ float sxs[16];
  int tid=threadIdx.x;
  int row0=blockIdx.x*16;
  if (tid<16) sxs[tid]=g_xs1[row0+tid];
  __syncthreads();
  for (int i=tid;i<16*HID;i+=256){
    int r=i>>9;
    float v = g_be0[row0*HID + i]/sxs[r];
    xn[r][i&511] = fminf(fmaxf(v,-1.f),1.f);
  }
  __syncthreads();
  int n0=tid, n1=tid+256;
  float a0[16], a1_[16];
  #pragma unroll
  for (int r=0;r<16;r++){ a0[r]=0.f; a1_[r]=0.f; }
  for (int k=0;k<HID;k+=4){
    float4 w0 = *(const float4*)&B1[n0*HID+k];
    float4 w1 = *(const float4*)&B1[n1*HID+k];
    #pragma unroll
    for (int r=0;r<16;r++){
      float4 x = *(const float4*)&xn[r][k];
      a0 [r] += w0.x*x.x + w0.y*x.y + w0.z*x.z + w0.w*x.w;
      a1_[r] += w1.x*x.x + w1.y*x.y + w1.z*x.z + w1.w*x.w;
    }
  }
  #pragma unroll
  for (int r=0;r<16;r++){
    g_be1[(row0+r)*HID+n0]=a0[r];
    g_be1[(row0+r)*HID+n1]=a1_[r];
  }
}

// ---------------- grid barrier (monotonic; counter reset by k_init) ----------------
__device__ __forceinline__ void gridbar(unsigned &target){
  __threadfence();
  __syncthreads();
  if (threadIdx.x==0){
    target += SER_NCTA;
    atomicAdd(&g_bcount, 1u);
    while (*((volatile unsigned*)&g_bcount) < target) { }
  }
  __syncthreads();
}

// ---------------- serial layer-1 recurrence ----------------
__global__ __launch_bounds__(SER_THREADS) void k_serial(
    const float* __restrict__ C1, const float* __restrict__ W1,
    const float* __restrict__ a1, const float* __restrict__ tau,
    const float* __restrict__ gam){
  __shared__ float xbuf[BQ*HID];   // staged h (phase1) / err (phase2)
  __shared__ float h_own[64];      // old h for this CTA's (b,n) slice
  __shared__ float siga[SER_NC];
  __shared__ float snorm[BQ];
  int tid=threadIdx.x, cta=blockIdx.x;
  int nbase=cta*SER_NC;
  if (tid<SER_NC) siga[tid]=sigm(a1[nbase+tid]);
  if (tid<BQ)     snorm[tid]=0.f;
  float tauv=tau[0], gamv=gam[0];
  int grp=tid>>2, l4=tid&3;
  int b=grp>>2, nl=grp&3;
  int nglob=nbase+nl;
  const float4* wc4 = (const float4*)&C1[nglob*HID];  // L1-resident across steps
  const float4* ww4 = (const float4*)&W1[nglob*HID];
  unsigned target=0;
  __syncthreads();

  for (int t=0;t<TT;t++){
    // ---- phase 1: p = tanh(h@C1^T)*xs ; err = be0 - p ; partial norms ----
    for (int i=tid;i<BQ*HID/4;i+=SER_THREADS)
      ((float4*)xbuf)[i] = __ldcg(((const float4*)g_h)+i);
    __syncthreads();
    if (l4==0) h_own[grp] = xbuf[b*HID+nglob];
    float xs = __ldg(&g_xs1[b*TT+t]);
    float acc=0.f;
    #pragma unroll
    for (int j=0;j<32;j++){
      float4 w = __ldg(&wc4[l4 + j*4]);
      float4 x = *(const float4*)&xbuf[b*HID + l4*4 + j*16];
      acc += w.x*x.x + w.y*x.y + w.z*x.z + w.w*x.w;
    }
    acc += __shfl_down_sync(0xffffffffu,acc,2);
    acc += __shfl_down_sync(0xffffffffu,acc,1);
    if (l4==0){
      float p = tanhf(acc)*xs;
      float e = __ldg(&g_be0[(b*TT+t)*HID+nglob]) - p;
      __stcg(&g_err[b*HID+nglob], e);
      atomicAdd(&snorm[b], e*e);
    }
    __syncthreads();
    if (tid<BQ){ atomicAdd(&g_norm2[t&1][tid], snorm[tid]); snorm[tid]=0.f; }
    gridbar(target);

    // ---- phase 2: surprise ; ee = err@W1^T ; h update ----
    if (cta==0 && tid<BQ) __stcg(&g_norm2[(t+1)&1][tid], 0.f);
    for (int i=tid;i<BQ*HID/4;i+=SER_THREADS)
      ((float4*)xbuf)[i] = __ldcg(((const float4*)g_err)+i);
    __syncthreads();
    float n2 = __ldcg(&g_norm2[t&1][b]);
    float rel = fminf(sqrtf(n2)/xs, 4.0f);
    float s = sigm((rel - tauv)/gamv);
    float acc2=0.f;
    #pragma unroll
    for (int j=0;j<32;j++){
      float4 w = __ldg(&ww4[l4 + j*4]);
      float4 x = *(const float4*)&xbuf[b*HID + l4*4 + j*16];
      acc2 += w.x*x.x + w.y*x.y + w.z*x.z + w.w*x.w;
    }
    acc2 += __shfl_down_sync(0xffffffffu,acc2,2);
    acc2 += __shfl_down_sync(0xffffffffu,acc2,1);
    if (l4==0){
      float hol = h_own[grp];
      float be1v = __ldg(&g_be1[(b*TT+t)*HID+nglob]);
      float ih = 0.2f*hol + 0.6f*be1v + 0.2f*s*acc2;
      float g = s*siga[nl];
      float hn = hol*(1.f-g) + tanhf(ih)*g;
      __stcg(&g_h[b*HID+nglob], hn);
      g_h1[(b*TT+t)*HID+nglob] = hn;
    }
    gridbar(target);
  }
}

// ---------------- head: out = [h1, be1] @ head_w^T + head_b ----------------
__global__ __launch_bounds__(256) void k_head(const float* __restrict__ hw,
                                              const float* __restrict__ hb,
                                              float* __restrict__ out){
  __shared__ float sh[8*1024];
  __shared__ float sred[4*8*64];
  int tid=threadIdx.x;
  int row0=blockIdx.x*8;
  for (int i=tid;i<8*1024;i+=256){
    int r=i>>10, j=i&1023;
    sh[i] = (j<512)? g_h1[(row0+r)*HID+j] : g_be1[(row0+r)*HID+(j-512)];
  }
  __syncthreads();
  int c=tid&63, q=tid>>6;
  float acc[8];
  #pragma unroll
  for (int r=0;r<8;r++) acc[r]=0.f;
  for (int k=q*256;k<q*256+256;k+=4){
    float4 w = *(const float4*)&hw[c*1024+k];
    #pragma unroll
    for (int r=0;r<8;r++){
      float4 x = *(const float4*)&sh[r*1024+k];
      acc[r] += w.x*x.x + w.y*x.y + w.z*x.z + w.w*x.w;
    }
  }
  #pragma unroll
  for (int r=0;r<8;r++) sred[(q*8+r)*64+c]=acc[r];
  __syncthreads();
  for (int i=tid;i<8*64;i+=256){
    int r=i>>6, cc=i&63;
    out[(row0+r)*NCLS+cc] = sred[r*64+cc] + sred[(8+r)*64+cc]
                          + sred[(16+r)*64+cc] + sred[(24+r)*64+cc] + __ldg(&hb[cc]);
  }
}

// ---------------- launch ----------------
extern "C" void kernel_launch(void* const* d_in, const int* in_sizes, int n_in,
                              void* d_out, int out_size){
  const float* feats=(const float*)d_in[0];
  const float* B0  =(const float*)d_in[2];
  const float* C1  =(const float*)d_in[7];
  const float* B1  =(const float*)d_in[8];
  const float* W1  =(const float*)d_in[9];
  const float* a1  =(const float*)d_in[10];
  const float* tau1=(const float*)d_in[11];
  const float* gam1=(const float*)d_in[12];
  const float* hw  =(const float*)d_in[13];
  const float* hb  =(const float*)d_in[14];
  float* out=(float*)d_out;

  k_init  <<<1,256>>>();
  k_be0   <<<NROW/16,256>>>(feats,B0);
  k_be1   <<<NROW/16,256>>>(B1);
  k_serial<<<SER_NCTA,SER_THREADS>>>(C1,W1,a1,tau1,gam1);
  k_head  <<<NROW/8,256>>>(hw,hb,out);
}

// round 5
// speedup vs baseline: 1.9192x; 1.9192x over previous
#include <cuda_runtime.h>
#include <math.h>
#include <stdint.h>

#define BQ   16
#define TT   1000
#define MEL  80
#define HID  512
#define NCLS 64
#define NROW (BQ*TT)

#define CLN  8      // CTAs per cluster
#define BPC  2      // batch elements per cluster
#define NCTA 64     // 8 clusters * 8 CTAs

// ---------------- scratch (static device globals; no allocations) ----------------
__device__ float g_be0[NROW*HID];     // base_eff of layer0 == input to layer1
__device__ float g_be1[NROW*HID];     // base_eff of layer1 (second half of ys)
__device__ float g_h1 [NROW*HID];     // h1 trace (first half of ys)
__device__ float g_xs1[NROW];         // per-(b,t) x_scale for layer1

__device__ __forceinline__ float sigm(float x){ return 1.0f/(1.0f+expf(-x)); }

__device__ __forceinline__ uint32_t smem_u32(const void* p){
  uint32_t a;
  asm("{ .reg .u64 t; cvta.to.shared.u64 t, %1; cvt.u32.u64 %0, t; }" : "=r"(a) : "l"(p));
  return a;
}
__device__ __forceinline__ void dsmem_st4(uint32_t laddr, uint32_t rnk, float4 v){
  uint32_t ra;
  asm volatile("mapa.shared::cluster.u32 %0, %1, %2;" : "=r"(ra) : "r"(laddr), "r"(rnk));
  asm volatile("st.shared::cluster.v4.f32 [%0], {%1,%2,%3,%4};"
               :: "r"(ra), "f"(v.x), "f"(v.y), "f"(v.z), "f"(v.w) : "memory");
}
__device__ __forceinline__ void dsmem_st1(uint32_t laddr, uint32_t rnk, float v){
  uint32_t ra;
  asm volatile("mapa.shared::cluster.u32 %0, %1, %2;" : "=r"(ra) : "r"(laddr), "r"(rnk));
  asm volatile("st.shared::cluster.f32 [%0], %1;" :: "r"(ra), "f"(v) : "memory");
}
#define CLUSTER_SYNC() do{ \
  asm volatile("barrier.cluster.arrive.aligned;" ::: "memory"); \
  asm volatile("barrier.cluster.wait.aligned;"  ::: "memory"); }while(0)

// ---------------- be0 = clip(feats/||feats||) @ B0^T ; xs1 = ||be0|| ----------------
__global__ __launch_bounds__(256) void k_be0(const float* __restrict__ feats,
                                             const float* __restrict__ B0){
  __shared__ float xn[16][MEL];
  __shared__ float snorm[16];
  __shared__ float sxs[16];
  int tid = threadIdx.x;
  int row0 = blockIdx.x*16;
  for (int i=tid;i<16*MEL;i+=256)
    xn[i/MEL][i%MEL] = feats[row0*MEL + i];
  __syncthreads();
  if (tid<16){
    float s=0.f;
    #pragma unroll
    for (int k=0;k<MEL;k++){ float v=xn[tid][k]; s+=v*v; }
    sxs[tid]=fmaxf(sqrtf(s),1e-6f);
    snorm[tid]=0.f;
  }
  __syncthreads();
  for (int i=tid;i<16*MEL;i+=256){
    int r=i/MEL;
    float v = xn[r][i%MEL]/sxs[r];
    xn[r][i%MEL] = fminf(fmaxf(v,-1.f),1.f);
  }
  __syncthreads();
  int n0=tid, n1=tid+256;
  float a0[16], a1_[16];
  #pragma unroll
  for (int r=0;r<16;r++){ a0[r]=0.f; a1_[r]=0.f; }
  for (int k=0;k<MEL;k+=4){
    float4 w0 = *(const float4*)&B0[n0*MEL+k];
    float4 w1 = *(const float4*)&B0[n1*MEL+k];
    #pragma unroll
    for (int r=0;r<16;r++){
      float4 x = *(const float4*)&xn[r][k];
      a0 [r] += w0.x*x.x + w0.y*x.y + w0.z*x.z + w0.w*x.w;
      a1_[r] += w1.x*x.x + w1.y*x.y + w1.z*x.z + w1.w*x.w;
    }
  }
  #pragma unroll
  for (int r=0;r<16;r++){
    g_be0[(row0+r)*HID+n0]=a0[r];
    g_be0[(row0+r)*HID+n1]=a1_[r];
    atomicAdd(&snorm[r], a0[r]*a0[r] + a1_[r]*a1_[r]);
  }
  __syncthreads();
  if (tid<16) g_xs1[row0+tid] = fmaxf(sqrtf(snorm[tid]),1e-6f);
}

// ---------------- be1 = clip(be0/xs1) @ B1^T ----------------
__global__ __launch_bounds__(256) void k_be1(const float* __restrict__ B1){
  __shared__ float xn[16][HID];
  __shared__ float sxs[16];
  int tid=threadIdx.x;
  int row0=blockIdx.x*16;
  if (tid<16) sxs[tid]=g_xs1[row0+tid];
  __syncthreads();
  for (int i=tid;i<16*HID;i+=256){
    int r=i>>9;
    float v = g_be0[row0*HID + i]/sxs[r];
    xn[r][i&511] = fminf(fmaxf(v,-1.f),1.f);
  }
  __syncthreads();
  int n0=tid, n1=tid+256;
  float a0[16], a1_[16];
  #pragma unroll
  for (int r=0;r<16;r++){ a0[r]=0.f; a1_[r]=0.f; }
  for (int k=0;k<HID;k+=4){
    float4 w0 = *(const float4*)&B1[n0*HID+k];
    float4 w1 = *(const float4*)&B1[n1*HID+k];
    #pragma unroll
    for (int r=0;r<16;r++){
      float4 x = *(const float4*)&xn[r][k];
      a0 [r] += w0.x*x.x + w0.y*x.y + w0.z*x.z + w0.w*x.w;
      a1_[r] += w1.x*x.x + w1.y*x.y + w1.z*x.z + w1.w*x.w;
    }
  }
  #pragma unroll
  for (int r=0;r<16;r++){
    g_be1[(row0+r)*HID+n0]=a0[r];
    g_be1[(row0+r)*HID+n1]=a1_[r];
  }
}

// ---------------- serial layer-1 recurrence: cluster of 8 CTAs per 2 batch elems ----
// CTA `rank` owns rows [rank*64, rank*64+64). Vectors exchanged by DSMEM push;
// phases separated by cluster barriers (no grid-wide sync, no L2 polling).
struct DotOut { float a[4][BPC]; };

__device__ __forceinline__ void dot_rows(const float* __restrict__ W,
                                         const float (&xb)[BPC][HID],
                                         int row0, int kq, DotOut& o){
  float a00=0.f,a01=0.f,a10=0.f,a11=0.f,a20=0.f,a21=0.f,a30=0.f,a31=0.f;
  const float* wp = W + row0*HID + kq*4;
  #pragma unroll
  for (int m=0;m<8;m++){
    int k0 = kq*4 + m*64;
    float4 x0 = *(const float4*)&xb[0][k0];
    float4 x1 = *(const float4*)&xb[1][k0];
    float4 w0 = __ldg((const float4*)(wp + 0*HID + m*64));
    float4 w1 = __ldg((const float4*)(wp + 1*HID + m*64));
    float4 w2 = __ldg((const float4*)(wp + 2*HID + m*64));
    float4 w3 = __ldg((const float4*)(wp + 3*HID + m*64));
    a00 += w0.x*x0.x + w0.y*x0.y + w0.z*x0.z + w0.w*x0.w;
    a01 += w0.x*x1.x + w0.y*x1.y + w0.z*x1.z + w0.w*x1.w;
    a10 += w1.x*x0.x + w1.y*x0.y + w1.z*x0.z + w1.w*x0.w;
    a11 += w1.x*x1.x + w1.y*x1.y + w1.z*x1.z + w1.w*x1.w;
    a20 += w2.x*x0.x + w2.y*x0.y + w2.z*x0.z + w2.w*x0.w;
    a21 += w2.x*x1.x + w2.y*x1.y + w2.z*x1.z + w2.w*x1.w;
    a30 += w3.x*x0.x + w3.y*x0.y + w3.z*x0.z + w3.w*x0.w;
    a31 += w3.x*x1.x + w3.y*x1.y + w3.z*x1.z + w3.w*x1.w;
  }
  #pragma unroll
  for (int off=8; off; off>>=1){
    a00 += __shfl_down_sync(0xffffffffu,a00,off);
    a01 += __shfl_down_sync(0xffffffffu,a01,off);
    a10 += __shfl_down_sync(0xffffffffu,a10,off);
    a11 += __shfl_down_sync(0xffffffffu,a11,off);
    a20 += __shfl_down_sync(0xffffffffu,a20,off);
    a21 += __shfl_down_sync(0xffffffffu,a21,off);
    a30 += __shfl_down_sync(0xffffffffu,a30,off);
    a31 += __shfl_down_sync(0xffffffffu,a31,off);
  }
  o.a[0][0]=a00; o.a[0][1]=a01; o.a[1][0]=a10; o.a[1][1]=a11;
  o.a[2][0]=a20; o.a[2][1]=a21; o.a[3][0]=a30; o.a[3][1]=a31;
}

__global__ __launch_bounds__(256,1) __cluster_dims__(CLN,1,1)
void k_serial(const float* __restrict__ C1, const float* __restrict__ W1,
              const float* __restrict__ a1, const float* __restrict__ tau,
              const float* __restrict__ gam){
  __shared__ __align__(16) float hbuf[BPC][HID];     // full h (both b) - remote-written
  __shared__ __align__(16) float ebuf[BPC][HID];     // full err        - remote-written
  __shared__ __align__(16) float estage[BPC][64];    // own err slice staging
  __shared__ __align__(16) float hstage[BPC][64];    // own new-h slice staging
  __shared__ float pout[64][BPC];                    // dot results (own rows)
  __shared__ float narr[BPC][CLN];                   // norm partials from each rank
  __shared__ float normloc[BPC];
  __shared__ float sa[64];                           // sigmoid(a1) for own rows

  const int tid  = threadIdx.x;
  const int rank = blockIdx.x & (CLN-1);
  const int b0   = (blockIdx.x / CLN) * BPC;
  const int rg   = tid >> 4, kq = tid & 15;
  const int row0 = rank*64 + rg*4;
  const float tauv = __ldg(&tau[0]), gamv = __ldg(&gam[0]);

  for (int i=tid;i<BPC*HID;i+=256) (&hbuf[0][0])[i]=0.f;
  if (tid<BPC) normloc[tid]=0.f;
  if (tid<64)  sa[tid] = sigm(__ldg(&a1[rank*64+tid]));
  __syncthreads();

  const uint32_t a_ebuf = smem_u32(&ebuf[0][0]);
  const uint32_t a_hbuf = smem_u32(&hbuf[0][0]);
  const uint32_t a_narr = smem_u32(&narr[0][0]);

  const int eb = tid & 1, erow = tid >> 1;           // epilogue mapping (tid<128)
  const int dest = tid >> 5, chunk = tid & 31;       // push mapping
  const int pb = chunk >> 4, pq = chunk & 15;
  const uint32_t e_off = (uint32_t)(pb*HID + rank*64 + pq*4)*4u;

  for (int t=0;t<TT;t++){
    // per-step scalars for epilogue threads (latency hidden under dot loop)
    float xsv=1.f, be0v=0.f, be1v=0.f;
    if (tid<128){
      int bb = b0+eb;
      xsv  = __ldg(&g_xs1[bb*TT+t]);
      be0v = __ldg(&g_be0[(bb*TT+t)*HID + rank*64 + erow]);
      be1v = __ldg(&g_be1[(bb*TT+t)*HID + rank*64 + erow]);
    }

    // ======== phase 1: p = h @ C1^T (own rows), err, norm partial ========
    {
      DotOut o; dot_rows(C1, hbuf, row0, kq, o);
      if (kq==0){
        #pragma unroll
        for (int j=0;j<4;j++){ pout[rg*4+j][0]=o.a[j][0]; pout[rg*4+j][1]=o.a[j][1]; }
      }
    }
    __syncthreads();
    if (tid<128){
      float p = tanhf(pout[erow][eb]) * xsv;
      float e = be0v - p;
      estage[eb][erow] = e;
      float q = e*e;
      #pragma unroll
      for (int off=16; off>=2; off>>=1) q += __shfl_xor_sync(0xffffffffu,q,off);
      if ((tid&31)<2) atomicAdd(&normloc[eb], q);
    }
    __syncthreads();
    // push err slice + norm partial to all 8 CTAs (incl. self)
    {
      float4 v = ((const float4*)estage)[chunk];
      dsmem_st4(a_ebuf + e_off, (uint32_t)dest, v);
      if (tid<16)
        dsmem_st1(a_narr + (uint32_t)(((tid&1)*CLN + rank)*4), (uint32_t)(tid>>1),
                  normloc[tid&1]);
    }
    CLUSTER_SYNC();

    // ======== phase 2: surprise, ee = err @ W1^T, h update ========
    {
      DotOut o; dot_rows(W1, ebuf, row0, kq, o);
      if (kq==0){
        #pragma unroll
        for (int j=0;j<4;j++){ pout[rg*4+j][0]=o.a[j][0]; pout[rg*4+j][1]=o.a[j][1]; }
      }
    }
    __syncthreads();
    if (tid<128){
      float n2 = narr[eb][0]+narr[eb][1]+narr[eb][2]+narr[eb][3]
               + narr[eb][4]+narr[eb][5]+narr[eb][6]+narr[eb][7];
      float rel = fminf(sqrtf(n2)/xsv, 4.0f);
      float s = sigm((rel - tauv)/gamv);
      float hold = hbuf[eb][rank*64+erow];
      float ih = 0.2f*hold + 0.6f*be1v + 0.2f*s*pout[erow][eb];
      float g = s*sa[erow];
      float hn = hold*(1.f-g) + tanhf(ih)*g;
      hstage[eb][erow] = hn;
      g_h1[((b0+eb)*TT+t)*HID + rank*64 + erow] = hn;
    } else if (tid<128+BPC){
      normloc[tid-128]=0.f;          // reset for next step (disjoint threads)
    }
    __syncthreads();
    // push new h slice to all 8 CTAs (incl. self)
    {
      float4 v = ((const float4*)hstage)[chunk];
      dsmem_st4(a_hbuf + e_off, (uint32_t)dest, v);
    }
    CLUSTER_SYNC();
  }
}

// ---------------- head: out = [h1, be1] @ head_w^T + head_b ----------------
__global__ __launch_bounds__(256) void k_head(const float* __restrict__ hw,
                                              const float* __restrict__ hb,
                                              float* __restrict__ out){
  __shared__ float sh[8*1024];
  __shared__ float sred[4*8*64];
  int tid=threadIdx.x;
  int row0=blockIdx.x*8;
  for (int i=tid;i<8*1024;i+=256){
    int r=i>>10, j=i&1023;
    sh[i] = (j<512)? g_h1[(row0+r)*HID+j] : g_be1[(row0+r)*HID+(j-512)];
  }
  __syncthreads();
  int c=tid&63, q=tid>>6;
  float acc[8];
  #pragma unroll
  for (int r=0;r<8;r++) acc[r]=0.f;
  for (int k=q*256;k<q*256+256;k+=4){
    float4 w = *(const float4*)&hw[c*1024+k];
    #pragma unroll
    for (int r=0;r<8;r++){
      float4 x = *(const float4*)&sh[r*1024+k];
      acc[r] += w.x*x.x + w.y*x.y + w.z*x.z + w.w*x.w;
    }
  }
  #pragma unroll
  for (int r=0;r<8;r++) sred[(q*8+r)*64+c]=acc[r];
  __syncthreads();
  for (int i=tid;i<8*64;i+=256){
    int r=i>>6, cc=i&63;
    out[(row0+r)*NCLS+cc] = sred[r*64+cc] + sred[(8+r)*64+cc]
                          + sred[(16+r)*64+cc] + sred[(24+r)*64+cc] + __ldg(&hb[cc]);
  }
}

// ---------------- launch ----------------
extern "C" void kernel_launch(void* const* d_in, const int* in_sizes, int n_in,
                              void* d_out, int out_size){
  const float* feats=(const float*)d_in[0];
  const float* B0  =(const float*)d_in[2];
  const float* C1  =(const float*)d_in[7];
  const float* B1  =(const float*)d_in[8];
  const float* W1  =(const float*)d_in[9];
  const float* a1  =(const float*)d_in[10];
  const float* tau1=(const float*)d_in[11];
  const float* gam1=(const float*)d_in[12];
  const float* hw  =(const float*)d_in[13];
  const float* hb  =(const float*)d_in[14];
  float* out=(float*)d_out;

  k_be0   <<<NROW/16,256>>>(feats,B0);
  k_be1   <<<NROW/16,256>>>(B1);
  k_serial<<<NCTA,256>>>(C1,W1,a1,tau1,gam1);
  k_head  <<<NROW/8,256>>>(hw,hb,out);
}

// round 6
// speedup vs baseline: 2.4925x; 1.2987x over previous
#include <cuda_runtime.h>
#include <cuda_bf16.h>
#include <math.h>
#include <stdint.h>

#define BQ   16
#define TT   1000
#define MEL  80
#define HID  512
#define NCLS 64
#define NROW (BQ*TT)

#define CLN  8      // CTAs per cluster
#define BPC  2      // batch elements per cluster
#define NCTA 64     // 8 clusters * 8 CTAs

#define WROWB 1040u                // bf16 row stride bytes (520 ushorts, pad vs conflicts)
#define WMATB (64u*WROWB)          // one 64-row matrix slice in smem
#define DYNSM (2u*WMATB)           // C1 slice + W1 slice = 133120 B

// ---------------- scratch (static device globals; no allocations) ----------------
__device__ float g_be0[NROW*HID];
__device__ float g_be1[NROW*HID];
__device__ float g_h1 [NROW*HID];
__device__ float g_xs1[NROW];

__device__ __forceinline__ float sigm(float x){ return 1.0f/(1.0f+expf(-x)); }

__device__ __forceinline__ uint32_t smem_u32(const void* p){
  uint32_t a;
  asm("{ .reg .u64 t; cvta.to.shared.u64 t, %1; cvt.u32.u64 %0, t; }" : "=r"(a) : "l"(p));
  return a;
}
__device__ __forceinline__ void dsmem_st4(uint32_t laddr, uint32_t rnk, float4 v){
  uint32_t ra;
  asm volatile("mapa.shared::cluster.u32 %0, %1, %2;" : "=r"(ra) : "r"(laddr), "r"(rnk));
  asm volatile("st.shared::cluster.v4.f32 [%0], {%1,%2,%3,%4};"
               :: "r"(ra), "f"(v.x), "f"(v.y), "f"(v.z), "f"(v.w) : "memory");
}
__device__ __forceinline__ void dsmem_st1(uint32_t laddr, uint32_t rnk, float v){
  uint32_t ra;
  asm volatile("mapa.shared::cluster.u32 %0, %1, %2;" : "=r"(ra) : "r"(laddr), "r"(rnk));
  asm volatile("st.shared::cluster.f32 [%0], %1;" :: "r"(ra), "f"(v) : "memory");
}
#define CLUSTER_SYNC() do{ \
  asm volatile("barrier.cluster.arrive.aligned;" ::: "memory"); \
  asm volatile("barrier.cluster.wait.aligned;"  ::: "memory"); }while(0)

// permuted float4-group position for x buffers: group g (=k/4) -> pos
__host__ __device__ __forceinline__ int xpos(int g){
  int j = g>>1;
  return ((j>>4)<<5) + ((g&1)<<4) + (j&15);
}

// ---------------- be0 = clip(feats/||feats||) @ B0^T ; xs1 = ||be0|| ----------------
__global__ __launch_bounds__(256) void k_be0(const float* __restrict__ feats,
                                             const float* __restrict__ B0){
  __shared__ float xn[16][MEL];
  __shared__ float snorm[16];
  __shared__ float sxs[16];
  int tid = threadIdx.x;
  int row0 = blockIdx.x*16;
  for (int i=tid;i<16*MEL;i+=256)
    xn[i/MEL][i%MEL] = feats[row0*MEL + i];
  __syncthreads();
  if (tid<16){
    float s=0.f;
    #pragma unroll
    for (int k=0;k<MEL;k++){ float v=xn[tid][k]; s+=v*v; }
    sxs[tid]=fmaxf(sqrtf(s),1e-6f);
    snorm[tid]=0.f;
  }
  __syncthreads();
  for (int i=tid;i<16*MEL;i+=256){
    int r=i/MEL;
    float v = xn[r][i%MEL]/sxs[r];
    xn[r][i%MEL] = fminf(fmaxf(v,-1.f),1.f);
  }
  __syncthreads();
  int n0=tid, n1=tid+256;
  float a0[16], a1_[16];
  #pragma unroll
  for (int r=0;r<16;r++){ a0[r]=0.f; a1_[r]=0.f; }
  for (int k=0;k<MEL;k+=4){
    float4 w0 = *(const float4*)&B0[n0*MEL+k];
    float4 w1 = *(const float4*)&B0[n1*MEL+k];
    #pragma unroll
    for (int r=0;r<16;r++){
      float4 x = *(const float4*)&xn[r][k];
      a0 [r] += w0.x*x.x + w0.y*x.y + w0.z*x.z + w0.w*x.w;
      a1_[r] += w1.x*x.x + w1.y*x.y + w1.z*x.z + w1.w*x.w;
    }
  }
  #pragma unroll
  for (int r=0;r<16;r++){
    g_be0[(row0+r)*HID+n0]=a0[r];
    g_be0[(row0+r)*HID+n1]=a1_[r];
    atomicAdd(&snorm[r], a0[r]*a0[r] + a1_[r]*a1_[r]);
  }
  __syncthreads();
  if (tid<16) g_xs1[row0+tid] = fmaxf(sqrtf(snorm[tid]),1e-6f);
}

// ---------------- be1 = clip(be0/xs1) @ B1^T ----------------
__global__ __launch_bounds__(256) void k_be1(const float* __restrict__ B1){
  __shared__ float xn[16][HID];
  __shared__ float sxs[16];
  int tid=threadIdx.x;
  int row0=blockIdx.x*16;
  if (tid<16) sxs[tid]=g_xs1[row0+tid];
  __syncthreads();
  for (int i=tid;i<16*HID;i+=256){
    int r=i>>9;
    float v = g_be0[row0*HID + i]/sxs[r];
    xn[r][i&511] = fminf(fmaxf(v,-1.f),1.f);
  }
  __syncthreads();
  int n0=tid, n1=tid+256;
  float a0[16], a1_[16];
  #pragma unroll
  for (int r=0;r<16;r++){ a0[r]=0.f; a1_[r]=0.f; }
  for (int k=0;k<HID;k+=4){
    float4 w0 = *(const float4*)&B1[n0*HID+k];
    float4 w1 = *(const float4*)&B1[n1*HID+k];
    #pragma unroll
    for (int r=0;r<16;r++){
      float4 x = *(const float4*)&xn[r][k];
      a0 [r] += w0.x*x.x + w0.y*x.y + w0.z*x.z + w0.w*x.w;
      a1_[r] += w1.x*x.x + w1.y*x.y + w1.z*x.z + w1.w*x.w;
    }
  }
  #pragma unroll
  for (int r=0;r<16;r++){
    g_be1[(row0+r)*HID+n0]=a0[r];
    g_be1[(row0+r)*HID+n1]=a1_[r];
  }
}

// ---------------- serial recurrence: bf16 weights resident in SMEM ----------------
// CTA `rank` owns rows [rank*64, rank*64+64). x vectors exchanged by DSMEM push
// in a 16B-group permuted layout (conflict-free LDS for the dot loop).
__device__ __forceinline__ void dot_bf16(const uint8_t* __restrict__ wsm,   // 64-row slice
                                         const uint8_t* __restrict__ xb,   // [2][512]f permuted
                                         int rg, int kq, float* __restrict__ acc){
  const uint8_t* wr = wsm + (unsigned)(rg*4)*WROWB + (unsigned)kq*16u;
  #pragma unroll
  for (int m=0;m<4;m++){
    float4 xa0 = *(const float4*)(xb + (m*32+kq)*16);
    float4 xa1 = *(const float4*)(xb + (m*32+16+kq)*16);
    float4 xb0 = *(const float4*)(xb + 2048 + (m*32+kq)*16);
    float4 xb1 = *(const float4*)(xb + 2048 + (m*32+16+kq)*16);
    #pragma unroll
    for (int r=0;r<4;r++){
      uint4 w = *(const uint4*)(wr + (unsigned)r*WROWB + (unsigned)m*256u);
      float w0=__uint_as_float(w.x<<16), w1=__uint_as_float(w.x&0xffff0000u);
      float w2=__uint_as_float(w.y<<16), w3=__uint_as_float(w.y&0xffff0000u);
      float w4=__uint_as_float(w.z<<16), w5=__uint_as_float(w.z&0xffff0000u);
      float w6=__uint_as_float(w.w<<16), w7=__uint_as_float(w.w&0xffff0000u);
      acc[r*2+0] += w0*xa0.x + w1*xa0.y + w2*xa0.z + w3*xa0.w
                  + w4*xa1.x + w5*xa1.y + w6*xa1.z + w7*xa1.w;
      acc[r*2+1] += w0*xb0.x + w1*xb0.y + w2*xb0.z + w3*xb0.w
                  + w4*xb1.x + w5*xb1.y + w6*xb1.z + w7*xb1.w;
    }
  }
}

__global__ __launch_bounds__(256,1) __cluster_dims__(CLN,1,1)
void k_serial(const float* __restrict__ C1, const float* __restrict__ W1,
              const float* __restrict__ a1, const float* __restrict__ tau,
              const float* __restrict__ gam){
  extern __shared__ __align__(16) uint8_t dynsm[];       // bf16 weight slices
  uint8_t* wsmC = dynsm;
  uint8_t* wsmW = dynsm + WMATB;

  __shared__ __align__(16) float hbuf[BPC][HID];     // permuted h   (remote-written)
  __shared__ __align__(16) float ebuf[BPC][HID];     // permuted err (remote-written)
  __shared__ __align__(16) float estage[BPC][64];
  __shared__ __align__(16) float hstage[BPC][64];
  __shared__ float pout[64][BPC];
  __shared__ float narr[BPC][CLN];
  __shared__ float normloc[BPC];
  __shared__ float sa[64];

  const int tid  = threadIdx.x;
  const int rank = blockIdx.x & (CLN-1);
  const int b0   = (blockIdx.x / CLN) * BPC;
  const int rg   = tid >> 4, kq = tid & 15;
  const float tauv = __ldg(&tau[0]), gamv = __ldg(&gam[0]);

  // -------- prologue: convert own weight slices fp32 -> bf16 smem --------
  for (int i=tid; i<64*128; i+=256){
    int row=i>>7, q=i&127;
    float4 vc = __ldg((const float4*)&C1[(rank*64+row)*HID + q*4]);
    float4 vw = __ldg((const float4*)&W1[(rank*64+row)*HID + q*4]);
    __nv_bfloat162 c0 = __floats2bfloat162_rn(vc.x, vc.y);
    __nv_bfloat162 c1 = __floats2bfloat162_rn(vc.z, vc.w);
    __nv_bfloat162 w0 = __floats2bfloat162_rn(vw.x, vw.y);
    __nv_bfloat162 w1 = __floats2bfloat162_rn(vw.z, vw.w);
    uint2 uc; uc.x = *(uint32_t*)&c0; uc.y = *(uint32_t*)&c1;
    uint2 uw; uw.x = *(uint32_t*)&w0; uw.y = *(uint32_t*)&w1;
    *(uint2*)(wsmC + (unsigned)row*WROWB + (unsigned)q*8u) = uc;
    *(uint2*)(wsmW + (unsigned)row*WROWB + (unsigned)q*8u) = uw;
  }
  for (int i=tid;i<BPC*HID;i+=256) (&hbuf[0][0])[i]=0.f;
  if (tid<BPC) normloc[tid]=0.f;
  if (tid<64)  sa[tid] = sigm(__ldg(&a1[rank*64+tid]));
  __syncthreads();

  const uint32_t a_ebuf = smem_u32(&ebuf[0][0]);
  const uint32_t a_hbuf = smem_u32(&hbuf[0][0]);
  const uint32_t a_narr = smem_u32(&narr[0][0]);

  const int eb = tid & 1, erow = tid >> 1;             // epilogue mapping (tid<128)
  const int dest = tid >> 5, chunk = tid & 31;         // push mapping
  const int pb = chunk >> 4, pq = chunk & 15;
  const uint32_t e_off = (uint32_t)(pb*2048 + xpos(rank*16 + pq)*16);
  // permuted index of own h element (for h_old read in epilogue)
  const int hk   = rank*64 + erow;
  const int hidx = eb*HID + xpos(hk>>2)*4 + (hk&3);

  for (int t=0;t<TT;t++){
    float xsv=1.f, be0v=0.f, be1v=0.f;
    if (tid<128){
      int bb = b0+eb;
      xsv  = __ldg(&g_xs1[bb*TT+t]);
      be0v = __ldg(&g_be0[(bb*TT+t)*HID + rank*64 + erow]);
      be1v = __ldg(&g_be1[(bb*TT+t)*HID + rank*64 + erow]);
    }

    // ======== phase 1: p = h @ C1^T (own rows), err, norm partial ========
    {
      float acc[8] = {0.f,0.f,0.f,0.f,0.f,0.f,0.f,0.f};
      dot_bf16(wsmC, (const uint8_t*)&hbuf[0][0], rg, kq, acc);
      #pragma unroll
      for (int off=8; off; off>>=1)
        #pragma unroll
        for (int j=0;j<8;j++) acc[j] += __shfl_down_sync(0xffffffffu, acc[j], off);
      if (kq==0){
        #pragma unroll
        for (int j=0;j<4;j++){ pout[rg*4+j][0]=acc[j*2]; pout[rg*4+j][1]=acc[j*2+1]; }
      }
    }
    __syncthreads();
    if (tid<128){
      float p = tanhf(pout[erow][eb]) * xsv;
      float e = be0v - p;
      estage[eb][erow] = e;
      float q = e*e;
      #pragma unroll
      for (int off=16; off>=2; off>>=1) q += __shfl_xor_sync(0xffffffffu,q,off);
      if ((tid&31)<2) atomicAdd(&normloc[eb], q);
    }
    __syncthreads();
    {
      float4 v = ((const float4*)estage)[chunk];
      dsmem_st4(a_ebuf + e_off, (uint32_t)dest, v);
      if (tid<16)
        dsmem_st1(a_narr + (uint32_t)(((tid&1)*CLN + rank)*4), (uint32_t)(tid>>1),
                  normloc[tid&1]);
    }
    CLUSTER_SYNC();

    // ======== phase 2: surprise, ee = err @ W1^T, h update ========
    {
      float acc[8] = {0.f,0.f,0.f,0.f,0.f,0.f,0.f,0.f};
      dot_bf16(wsmW, (const uint8_t*)&ebuf[0][0], rg, kq, acc);
      #pragma unroll
      for (int off=8; off; off>>=1)
        #pragma unroll
        for (int j=0;j<8;j++) acc[j] += __shfl_down_sync(0xffffffffu, acc[j], off);
      if (kq==0){
        #pragma unroll
        for (int j=0;j<4;j++){ pout[rg*4+j][0]=acc[j*2]; pout[rg*4+j][1]=acc[j*2+1]; }
      }
    }
    __syncthreads();
    if (tid<128){
      float n2 = narr[eb][0]+narr[eb][1]+narr[eb][2]+narr[eb][3]
               + narr[eb][4]+narr[eb][5]+narr[eb][6]+narr[eb][7];
      float rel = fminf(sqrtf(n2)/xsv, 4.0f);
      float s = sigm((rel - tauv)/gamv);
      float hold = (&hbuf[0][0])[hidx];
      float ih = 0.2f*hold + 0.6f*be1v + 0.2f*s*pout[erow][eb];
      float g = s*sa[erow];
      float hn = hold*(1.f-g) + tanhf(ih)*g;
      hstage[eb][erow] = hn;
      g_h1[((b0+eb)*TT+t)*HID + rank*64 + erow] = hn;
    } else if (tid<128+BPC){
      normloc[tid-128]=0.f;
    }
    __syncthreads();
    {
      float4 v = ((const float4*)hstage)[chunk];
      dsmem_st4(a_hbuf + e_off, (uint32_t)dest, v);
    }
    CLUSTER_SYNC();
  }
}

// ---------------- head: out = [h1, be1] @ head_w^T + head_b ----------------
__global__ __launch_bounds__(256) void k_head(const float* __restrict__ hw,
                                              const float* __restrict__ hb,
                                              float* __restrict__ out){
  __shared__ float sh[8*1024];
  __shared__ float sred[4*8*64];
  int tid=threadIdx.x;
  int row0=blockIdx.x*8;
  for (int i=tid;i<8*1024;i+=256){
    int r=i>>10, j=i&1023;
    sh[i] = (j<512)? g_h1[(row0+r)*HID+j] : g_be1[(row0+r)*HID+(j-512)];
  }
  __syncthreads();
  int c=tid&63, q=tid>>6;
  float acc[8];
  #pragma unroll
  for (int r=0;r<8;r++) acc[r]=0.f;
  for (int k=q*256;k<q*256+256;k+=4){
    float4 w = *(const float4*)&hw[c*1024+k];
    #pragma unroll
    for (int r=0;r<8;r++){
      float4 x = *(const float4*)&sh[r*1024+k];
      acc[r] += w.x*x.x + w.y*x.y + w.z*x.z + w.w*x.w;
    }
  }
  #pragma unroll
  for (int r=0;r<8;r++) sred[(q*8+r)*64+c]=acc[r];
  __syncthreads();
  for (int i=tid;i<8*64;i+=256){
    int r=i>>6, cc=i&63;
    out[(row0+r)*NCLS+cc] = sred[r*64+cc] + sred[(8+r)*64+cc]
                          + sred[(16+r)*64+cc] + sred[(24+r)*64+cc] + __ldg(&hb[cc]);
  }
}

// ---------------- launch ----------------
extern "C" void kernel_launch(void* const* d_in, const int* in_sizes, int n_in,
                              void* d_out, int out_size){
  const float* feats=(const float*)d_in[0];
  const float* B0  =(const float*)d_in[2];
  const float* C1  =(const float*)d_in[7];
  const float* B1  =(const float*)d_in[8];
  const float* W1  =(const float*)d_in[9];
  const float* a1  =(const float*)d_in[10];
  const float* tau1=(const float*)d_in[11];
  const float* gam1=(const float*)d_in[12];
  const float* hw  =(const float*)d_in[13];
  const float* hb  =(const float*)d_in[14];
  float* out=(float*)d_out;

  static int smem_set = 0;
  if (!smem_set){
    cudaFuncSetAttribute(k_serial, cudaFuncAttributeMaxDynamicSharedMemorySize, DYNSM);
    smem_set = 1;
  }

  k_be0   <<<NROW/16,256>>>(feats,B0);
  k_be1   <<<NROW/16,256>>>(B1);
  k_serial<<<NCTA,256,DYNSM>>>(C1,W1,a1,tau1,gam1);
  k_head  <<<NROW/8,256>>>(hw,hb,out);
}